// round 14
// baseline (speedup 1.0000x reference)
#include <cuda_runtime.h>
#include <cuda_fp16.h>
#include <cstdint>

#define Tn  4096
#define Hd  2048
#define En  8
#define Id  1024
#define ISd 4096

#define BM 128
#define NTH 256

// smem: 3 stages of 32KB (A 16KB + B 16KB, fp16 128B rows); list after.
#define SM_STAGE 32768
#define SM_BOFF  16384
#define SM_LIST  98304
#define SMEM_BYTES 98816

typedef unsigned uns;

// ---------------- device scratch -------------------------------------------
__device__ int   g_cnt[En];
__device__ int   g_list[En * Tn];
__device__ float g_scores[Tn * 2];
__device__ __half g_Hm[(size_t)Tn * 2 * Id];
__device__ __half g_Sm[(size_t)Tn * ISd];
__device__ float g_Y[(size_t)Tn * 2 * Hd];
// pre-converted fp16 operands
__device__ __half g_xF[(size_t)Tn * Hd];
__device__ __half g_gwF[(size_t)En * Id * Hd];
__device__ __half g_uwF[(size_t)En * Id * Hd];
__device__ __half g_dwF[(size_t)En * Hd * Id];
__device__ __half g_sgwF[(size_t)ISd * Hd];
__device__ __half g_suwF[(size_t)ISd * Hd];
__device__ __half g_sdwF[(size_t)Hd * ISd];

// ---------------- helpers --------------------------------------------------
__device__ __forceinline__ uint32_t smem_u32(const void* p) {
    uint32_t a;
    asm("{ .reg .u64 t; cvta.to.shared.u64 t, %1; cvt.u32.u64 %0, t; }" : "=r"(a) : "l"(p));
    return a;
}
__device__ __forceinline__ void ldsm4(uns r[4], uint32_t a) {
    asm volatile("ldmatrix.sync.aligned.m8n8.x4.shared.b16 {%0,%1,%2,%3}, [%4];"
        : "=r"(r[0]), "=r"(r[1]), "=r"(r[2]), "=r"(r[3]) : "r"(a));
}
__device__ __forceinline__ void mma16816(float c[4], const uns a[4], const uns b[2]) {
    asm volatile("mma.sync.aligned.m16n8k16.row.col.f32.f16.f16.f32 "
        "{%0,%1,%2,%3}, {%4,%5,%6,%7}, {%8,%9}, {%0,%1,%2,%3};"
        : "+f"(c[0]), "+f"(c[1]), "+f"(c[2]), "+f"(c[3])
        : "r"(a[0]), "r"(a[1]), "r"(a[2]), "r"(a[3]), "r"(b[0]), "r"(b[1]));
}
__device__ __forceinline__ void cpa16(uint32_t d, const void* s, uint32_t bytes) {
    asm volatile("cp.async.ca.shared.global [%0], [%1], 16, %2;"
        :: "r"(d), "l"(s), "r"(bytes) : "memory");
}
__device__ __forceinline__ void cpcommit() {
    asm volatile("cp.async.commit_group;" ::: "memory");
}
template<int N> __device__ __forceinline__ void cpwait() {
    asm volatile("cp.async.wait_group %0;" :: "n"(N) : "memory");
}
__device__ __forceinline__ float siluf(float x) { return x / (1.f + expf(-x)); }

// ---------------- pre-convert fp32 -> fp16 ----------------------------------
__global__ void k_cvt(const float4* __restrict__ in, uint2* __restrict__ o, int n4) {
    int i = blockIdx.x * blockDim.x + threadIdx.x;
    if (i < n4) {
        float4 v = in[i];
        __half2 a = __floats2half2_rn(v.x, v.y);
        __half2 b = __floats2half2_rn(v.z, v.w);
        o[i] = make_uint2(*reinterpret_cast<uns*>(&a), *reinterpret_cast<uns*>(&b));
    }
}

// ---------------- router -----------------------------------------------------
__global__ void k_zero() {
    if (threadIdx.x < En) g_cnt[threadIdx.x] = 0;
}

__global__ void k_router(const float* __restrict__ x,
                         const float* __restrict__ rw,
                         float* __restrict__ logits) {
    int t = blockIdx.x;
    int w = threadIdx.x >> 5, lane = threadIdx.x & 31;
    const float* xt = x + (size_t)t * Hd;
    const float* we = rw + (size_t)w * Hd;
    float s = 0.f;
    for (int i = lane * 4; i < Hd; i += 128) {
        float4 xv = *(const float4*)(xt + i);
        float4 wv = *(const float4*)(we + i);
        s += xv.x * wv.x + xv.y * wv.y + xv.z * wv.z + xv.w * wv.w;
    }
    #pragma unroll
    for (int o = 16; o; o >>= 1) s += __shfl_xor_sync(0xffffffffu, s, o);
    __shared__ float lg[En];
    if (!lane) lg[w] = s;
    __syncthreads();
    if (threadIdx.x == 0) {
        #pragma unroll
        for (int e = 0; e < En; e++) logits[(size_t)t * En + e] = lg[e];
        int i0 = 0; float v0 = lg[0];
        #pragma unroll
        for (int e = 1; e < En; e++) if (lg[e] > v0) { v0 = lg[e]; i0 = e; }
        int i1 = -1; float v1 = -3.4e38f;
        #pragma unroll
        for (int e = 0; e < En; e++) if (e != i0 && lg[e] > v1) { v1 = lg[e]; i1 = e; }
        int p0 = t * 2, p1 = t * 2 + 1;
        g_scores[p0] = 1.f / (1.f + expf(-v0));
        g_scores[p1] = 1.f / (1.f + expf(-v1));
        int pos0 = atomicAdd(&g_cnt[i0], 1); g_list[i0 * Tn + pos0] = p0;
        int pos1 = atomicAdd(&g_cnt[i1], 1); g_list[i1 * Tn + pos1] = p1;
    }
}

// ---------------- unified mma.sync GEMM (single-MMA fp16, K-chunk 64) -------
// MODE 0: expert gate+up FUSED  A=x(gather)  B=gw|uw interleaved   K=2048 -> Hm
// MODE 1: shared gate+up FUSED  A=x          B=sgw|suw interleaved K=2048 -> Sm
// MODE 2: expert down           A=Hm         B=dw                  K=1024 -> g_Y
// MODE 3: shared down           A=Sm         B=sdw                 K=4096 -> out (+Y)
template<int MODE>
__global__ __launch_bounds__(NTH, 2) void k_gemm(float* __restrict__ out) {
    extern __shared__ __align__(1024) char smem[];
    const uint32_t sb = smem_u32(smem);
    const int tid = threadIdx.x, wid = tid >> 5, lane = tid & 31;

    constexpr bool EXP = (MODE == 0 || MODE == 2);
    constexpr bool GUP = (MODE == 0 || MODE == 1);
    constexpr int  KT  = GUP ? 2048 : (MODE == 2 ? 1024 : 4096);
    constexpr int  NKC = KT / 64;

    const int e   = EXP ? blockIdx.z : 0;
    const int cnt = EXP ? g_cnt[e] : Tn;
    const int m0  = blockIdx.x * BM;
    if (EXP && m0 >= cnt) return;
    const int n0  = GUP ? blockIdx.y * 64 : blockIdx.y * 128;

    int* sl = (int*)(smem + SM_LIST);
    if (EXP) {
        if (tid < 128) sl[tid] = (m0 + tid < cnt) ? g_list[e * Tn + m0 + tid] : -1;
        __syncthreads();
    }

    // ---- per-thread cp.async source rows (row = tid>>1, sub = tid&1) ----
    const int arow = tid >> 1, sub = tid & 1;
    bool aval = true;
    const __half *aF, *bF;
    if (MODE == 0) {
        int p = sl[arow]; aval = (p >= 0);
        aF = g_xF + (size_t)(aval ? (p >> 1) : 0) * Hd;
    } else if (MODE == 1) {
        aF = g_xF + (size_t)(m0 + arow) * Hd;
    } else if (MODE == 2) {
        int p = sl[arow]; aval = (p >= 0);
        aF = g_Hm + (size_t)(aval ? p : 0) * Id;
    } else {
        aF = g_Sm + (size_t)(m0 + arow) * ISd;
    }
    if (GUP) {
        const int j = (arow >> 3) & 1;
        const int srow = n0 + (arow >> 4) * 8 + (arow & 7);
        if (MODE == 0) bF = (j ? g_uwF : g_gwF) + ((size_t)e * Id + srow) * Hd;
        else           bF = (j ? g_suwF : g_sgwF) + (size_t)srow * Hd;
    } else if (MODE == 2) {
        bF = g_dwF + ((size_t)e * Hd + n0 + arow) * Id;
    } else {
        bF = g_sdwF + (size_t)(n0 + arow) * ISd;
    }

    const uint32_t avB = aval ? 16u : 0u;
    // store offsets: 128B rows, swizzle (row&7)<<4 on 16B units
    const uint32_t vst = (uint32_t)(arow & 7) << 4;
    const uint32_t o0 = ((uint32_t)(sub * 64))      ^ vst;
    const uint32_t o1 = ((uint32_t)(sub * 64 + 16)) ^ vst;
    const uint32_t o2 = ((uint32_t)(sub * 64 + 32)) ^ vst;
    const uint32_t o3 = ((uint32_t)(sub * 64 + 48)) ^ vst;
    const uint32_t aDst0 = sb + arow * 128;
    const uint32_t bDst0 = sb + SM_BOFF + arow * 128;

    // ---- mma-side ldmatrix bases ----
    const int wm = wid & 3, wn = wid >> 2;
    const uint32_t vA   = (uint32_t)(lane & 7) << 4;
    const uint32_t aLmB = (wm * 32 + (lane & 15)) * 128;
    const uint32_t aLmK = (lane >> 4) * 16;
    const uint32_t bLmRow = wn * 64 + ((lane >> 4) & 1) * 8 + (lane & 7);
    const uint32_t bLmB = SM_BOFF + bLmRow * 128;
    const uint32_t vB   = (uint32_t)(bLmRow & 7) << 4;
    const uint32_t bCol = ((lane >> 3) & 1) * 16;

    float acc[2][8][4];
    #pragma unroll
    for (int mt = 0; mt < 2; mt++)
        #pragma unroll
        for (int nt = 0; nt < 8; nt++)
            #pragma unroll
            for (int j = 0; j < 4; j++) acc[mt][nt][j] = 0.f;

    auto ISSUE = [&](int kc, int st) {
        const uint32_t aD = aDst0 + st * SM_STAGE;
        const uint32_t bD = bDst0 + st * SM_STAGE;
        const char* sA = (const char*)aF + kc * 128 + sub * 64;
        const char* sB = (const char*)bF + kc * 128 + sub * 64;
        cpa16(aD + o0, sA, avB);       cpa16(aD + o1, sA + 16, avB);
        cpa16(aD + o2, sA + 32, avB);  cpa16(aD + o3, sA + 48, avB);
        cpa16(bD + o0, sB, 16u);       cpa16(bD + o1, sB + 16, 16u);
        cpa16(bD + o2, sB + 32, 16u);  cpa16(bD + o3, sB + 48, 16u);
        cpcommit();
    };

    auto MMA = [&](int st) {
        const uint32_t aS = sb + st * SM_STAGE;
        #pragma unroll
        for (int h = 0; h < 4; h++) {
            uns Ah[2][4];
            #pragma unroll
            for (int mt = 0; mt < 2; mt++)
                ldsm4(Ah[mt], aS + aLmB + mt * 2048 + ((h * 32 + aLmK) ^ vA));
            #pragma unroll
            for (int ntp = 0; ntp < 4; ntp++) {
                uns B4[4];
                ldsm4(B4, aS + bLmB + ntp * 2048 + ((h * 32 + bCol) ^ vB));
                #pragma unroll
                for (int j = 0; j < 2; j++) {
                    const int nt = ntp * 2 + j;
                    #pragma unroll
                    for (int mt = 0; mt < 2; mt++)
                        mma16816(acc[mt][nt], Ah[mt], B4 + j * 2);
                }
            }
        }
    };

    // 3-stage pipeline, one barrier per chunk, 2 chunks in flight.
    ISSUE(0, 0); ISSUE(1, 1);
    for (int kc = 0; kc < NKC; kc++) {
        if (kc + 1 >= NKC) cpwait<0>(); else cpwait<1>();
        __syncthreads();
        if (kc + 2 < NKC) ISSUE(kc + 2, (kc + 2) % 3);
        MMA(kc % 3);
    }

    // ---- epilogue ----
    const int rb = wm * 32 + (lane >> 2);
    const int cq = (lane & 3) * 2;
    #pragma unroll
    for (int mt = 0; mt < 2; mt++) {
        #pragma unroll
        for (int rr = 0; rr < 2; rr++) {
            const int row = rb + mt * 16 + rr * 8;
            if (GUP) {
                float s; size_t base;
                if (MODE == 0) {
                    int p = sl[row];
                    if (p < 0) continue;
                    s = g_scores[p];
                    base = (size_t)p * Id;
                } else {
                    s = 1.f;
                    base = (size_t)(m0 + row) * ISd;
                }
                #pragma unroll
                for (int i = 0; i < 4; i++) {
                    float g0 = acc[mt][2 * i][rr * 2],     g1 = acc[mt][2 * i][rr * 2 + 1];
                    float u0 = acc[mt][2 * i + 1][rr * 2], u1 = acc[mt][2 * i + 1][rr * 2 + 1];
                    float h0, h1;
                    if (MODE == 0) { h0 = siluf(s * g0) * (s * u0); h1 = siluf(s * g1) * (s * u1); }
                    else           { h0 = siluf(g0) * u0;           h1 = siluf(g1) * u1; }
                    __half2 hp = __floats2half2_rn(h0, h1);
                    size_t idx = base + (size_t)(n0 + (wn * 4 + i) * 8 + cq);
                    if (MODE == 0) *(uns*)(g_Hm + idx) = *reinterpret_cast<uns*>(&hp);
                    else           *(uns*)(g_Sm + idx) = *reinterpret_cast<uns*>(&hp);
                }
            } else if (MODE == 2) {
                int p = sl[row];
                if (p < 0) continue;
                float* dst = g_Y + (size_t)p * Hd + n0 + wn * 64 + cq;
                #pragma unroll
                for (int nt = 0; nt < 8; nt++)
                    *(float2*)(dst + nt * 8) =
                        make_float2(acc[mt][nt][rr * 2], acc[mt][nt][rr * 2 + 1]);
            } else {
                const int t = m0 + row;
                size_t col = (size_t)(n0 + wn * 64 + cq);
                const float* y0 = g_Y + (size_t)(2 * t) * Hd + col;
                const float* y1 = g_Y + (size_t)(2 * t + 1) * Hd + col;
                float* dst = out + (size_t)t * Hd + col;
                #pragma unroll
                for (int nt = 0; nt < 8; nt++) {
                    float2 a = make_float2(acc[mt][nt][rr * 2], acc[mt][nt][rr * 2 + 1]);
                    float2 p0 = *(const float2*)(y0 + nt * 8);
                    float2 p1 = *(const float2*)(y1 + nt * 8);
                    a.x += p0.x + p1.x; a.y += p0.y + p1.y;
                    *(float2*)(dst + nt * 8) = a;
                }
            }
        }
    }
}

// ---------------- launch ----------------------------------------------------
extern "C" void kernel_launch(void* const* d_in, const int* in_sizes, int n_in,
                              void* d_out, int out_size) {
    const float* x   = (const float*)d_in[0];
    const float* rw  = (const float*)d_in[1];
    const float* gw  = (const float*)d_in[2];
    const float* uw  = (const float*)d_in[3];
    const float* dw  = (const float*)d_in[4];
    const float* sgw = (const float*)d_in[5];
    const float* suw = (const float*)d_in[6];
    const float* sdw = (const float*)d_in[7];
    float* out = (float*)d_out;
    float* logits = out + (size_t)Tn * Hd;

    cudaFuncSetAttribute(k_gemm<0>, cudaFuncAttributeMaxDynamicSharedMemorySize, SMEM_BYTES);
    cudaFuncSetAttribute(k_gemm<1>, cudaFuncAttributeMaxDynamicSharedMemorySize, SMEM_BYTES);
    cudaFuncSetAttribute(k_gemm<2>, cudaFuncAttributeMaxDynamicSharedMemorySize, SMEM_BYTES);
    cudaFuncSetAttribute(k_gemm<3>, cudaFuncAttributeMaxDynamicSharedMemorySize, SMEM_BYTES);

    __half *xF, *gwF, *uwF, *dwF, *sgwF, *suwF, *sdwF;
    cudaGetSymbolAddress((void**)&xF, g_xF);
    cudaGetSymbolAddress((void**)&gwF, g_gwF); cudaGetSymbolAddress((void**)&uwF, g_uwF);
    cudaGetSymbolAddress((void**)&dwF, g_dwF);
    cudaGetSymbolAddress((void**)&sgwF, g_sgwF); cudaGetSymbolAddress((void**)&suwF, g_suwF);
    cudaGetSymbolAddress((void**)&sdwF, g_sdwF);

    k_zero<<<1, 32>>>();
    k_router<<<Tn, 256>>>(x, rw, logits);

    const int nX = Tn * Hd / 4, nW = En * Id * Hd / 4, nS = ISd * Hd / 4;
    k_cvt<<<nX / 256, 256>>>((const float4*)x,   (uint2*)xF,   nX);
    k_cvt<<<nW / 256, 256>>>((const float4*)gw,  (uint2*)gwF,  nW);
    k_cvt<<<nW / 256, 256>>>((const float4*)uw,  (uint2*)uwF,  nW);
    k_cvt<<<nW / 256, 256>>>((const float4*)dw,  (uint2*)dwF,  nW);
    k_cvt<<<nS / 256, 256>>>((const float4*)sgw, (uint2*)sgwF, nS);
    k_cvt<<<nS / 256, 256>>>((const float4*)suw, (uint2*)suwF, nS);
    k_cvt<<<nS / 256, 256>>>((const float4*)sdw, (uint2*)sdwF, nS);

    k_gemm<0><<<dim3(Tn / BM, Id / 64, En),  NTH, SMEM_BYTES>>>(nullptr);
    k_gemm<2><<<dim3(Tn / BM, Hd / 128, En), NTH, SMEM_BYTES>>>(nullptr);
    k_gemm<1><<<dim3(Tn / BM, ISd / 64, 1),  NTH, SMEM_BYTES>>>(nullptr);
    k_gemm<3><<<dim3(Tn / BM, Hd / 128, 1),  NTH, SMEM_BYTES>>>(out);
}

// round 16
// speedup vs baseline: 1.0459x; 1.0459x over previous
#include <cuda_runtime.h>
#include <cuda_fp16.h>
#include <cstdint>

#define Tn  4096
#define Hd  2048
#define En  8
#define Id  1024
#define ISd 4096

#define BM 128
#define NTH 256

// smem: 4 stages of 16KB (A 8KB fp16 + B 8KB fp16); list after.
#define SM_STAGE 16384
#define SM_BOFF  8192
#define SM_LIST  65536
#define SMEM_BYTES 66048

typedef unsigned uns;

// ---------------- device scratch -------------------------------------------
__device__ int   g_cnt[En];
__device__ int   g_list[En * Tn];
__device__ float g_scores[Tn * 2];
__device__ __half g_Hm[(size_t)Tn * 2 * Id];
__device__ __half g_Sm[(size_t)Tn * ISd];
__device__ float g_Y[(size_t)Tn * 2 * Hd];
// pre-converted fp16 operands
__device__ __half g_xF[(size_t)Tn * Hd];
__device__ __half g_gwF[(size_t)En * Id * Hd];
__device__ __half g_uwF[(size_t)En * Id * Hd];
__device__ __half g_dwF[(size_t)En * Hd * Id];
__device__ __half g_sgwF[(size_t)ISd * Hd];
__device__ __half g_suwF[(size_t)ISd * Hd];
__device__ __half g_sdwF[(size_t)Hd * ISd];

// ---------------- helpers --------------------------------------------------
__device__ __forceinline__ uint32_t smem_u32(const void* p) {
    uint32_t a;
    asm("{ .reg .u64 t; cvta.to.shared.u64 t, %1; cvt.u32.u64 %0, t; }" : "=r"(a) : "l"(p));
    return a;
}
__device__ __forceinline__ void ldsm4(uns r[4], uint32_t a) {
    asm volatile("ldmatrix.sync.aligned.m8n8.x4.shared.b16 {%0,%1,%2,%3}, [%4];"
        : "=r"(r[0]), "=r"(r[1]), "=r"(r[2]), "=r"(r[3]) : "r"(a));
}
__device__ __forceinline__ void mma16816(float c[4], const uns a[4], const uns b[2]) {
    asm volatile("mma.sync.aligned.m16n8k16.row.col.f32.f16.f16.f32 "
        "{%0,%1,%2,%3}, {%4,%5,%6,%7}, {%8,%9}, {%0,%1,%2,%3};"
        : "+f"(c[0]), "+f"(c[1]), "+f"(c[2]), "+f"(c[3])
        : "r"(a[0]), "r"(a[1]), "r"(a[2]), "r"(a[3]), "r"(b[0]), "r"(b[1]));
}
__device__ __forceinline__ void cpa16(uint32_t d, const void* s, uint32_t bytes) {
    asm volatile("cp.async.ca.shared.global [%0], [%1], 16, %2;"
        :: "r"(d), "l"(s), "r"(bytes) : "memory");
}
__device__ __forceinline__ void cpcommit() {
    asm volatile("cp.async.commit_group;" ::: "memory");
}
template<int N> __device__ __forceinline__ void cpwait() {
    asm volatile("cp.async.wait_group %0;" :: "n"(N) : "memory");
}
__device__ __forceinline__ float siluf(float x) { return x / (1.f + expf(-x)); }

// ---------------- fused pre-convert fp32 -> fp16 (all 7 tensors) ------------
// global float4 index space (units of 1M = 1<<20 float4):
// x:[0,2) gw:[2,6) uw:[6,10) dw:[10,14) sgw:[14,16) suw:[16,18) sdw:[18,20)
__global__ void k_cvtall(const float4* __restrict__ x,  const float4* __restrict__ gw,
                         const float4* __restrict__ uw, const float4* __restrict__ dw,
                         const float4* __restrict__ sgw, const float4* __restrict__ suw,
                         const float4* __restrict__ sdw) {
    const unsigned M = 1u << 20;
    unsigned b = blockIdx.x * 1024u;       // block covers 1024 float4s (4/thread)
    const float4* src; __half* dsth; unsigned w0;
    if      (b < 2*M)  { src = x;   dsth = g_xF;   w0 = b; }
    else if (b < 6*M)  { src = gw;  dsth = g_gwF;  w0 = b - 2*M; }
    else if (b < 10*M) { src = uw;  dsth = g_uwF;  w0 = b - 6*M; }
    else if (b < 14*M) { src = dw;  dsth = g_dwF;  w0 = b - 10*M; }
    else if (b < 16*M) { src = sgw; dsth = g_sgwF; w0 = b - 14*M; }
    else if (b < 18*M) { src = suw; dsth = g_suwF; w0 = b - 16*M; }
    else               { src = sdw; dsth = g_sdwF; w0 = b - 18*M; }
    uint2* dst = (uint2*)dsth;
    unsigned w = w0 + threadIdx.x;
    float4 v0 = src[w];
    float4 v1 = src[w + 256];
    float4 v2 = src[w + 512];
    float4 v3 = src[w + 768];
    #define CVT2(v) make_uint2(__half2_raw(__floats2half2_rn((v).x,(v).y)).x | \
                    ((uns)__half2_raw(__floats2half2_rn((v).x,(v).y)).y<<16), 0)
    #undef CVT2
    {
        __half2 a0 = __floats2half2_rn(v0.x, v0.y), b0h = __floats2half2_rn(v0.z, v0.w);
        dst[w]       = make_uint2(*(uns*)&a0, *(uns*)&b0h);
        __half2 a1 = __floats2half2_rn(v1.x, v1.y), b1h = __floats2half2_rn(v1.z, v1.w);
        dst[w + 256] = make_uint2(*(uns*)&a1, *(uns*)&b1h);
        __half2 a2 = __floats2half2_rn(v2.x, v2.y), b2h = __floats2half2_rn(v2.z, v2.w);
        dst[w + 512] = make_uint2(*(uns*)&a2, *(uns*)&b2h);
        __half2 a3 = __floats2half2_rn(v3.x, v3.y), b3h = __floats2half2_rn(v3.z, v3.w);
        dst[w + 768] = make_uint2(*(uns*)&a3, *(uns*)&b3h);
    }
}

// ---------------- router -----------------------------------------------------
__global__ void k_zero() {
    if (threadIdx.x < En) g_cnt[threadIdx.x] = 0;
}

__global__ void k_router(const float* __restrict__ x,
                         const float* __restrict__ rw,
                         float* __restrict__ logits) {
    int t = blockIdx.x;
    int w = threadIdx.x >> 5, lane = threadIdx.x & 31;
    const float* xt = x + (size_t)t * Hd;
    const float* we = rw + (size_t)w * Hd;
    float s = 0.f;
    for (int i = lane * 4; i < Hd; i += 128) {
        float4 xv = *(const float4*)(xt + i);
        float4 wv = *(const float4*)(we + i);
        s += xv.x * wv.x + xv.y * wv.y + xv.z * wv.z + xv.w * wv.w;
    }
    #pragma unroll
    for (int o = 16; o; o >>= 1) s += __shfl_xor_sync(0xffffffffu, s, o);
    __shared__ float lg[En];
    if (!lane) lg[w] = s;
    __syncthreads();
    if (threadIdx.x == 0) {
        #pragma unroll
        for (int e = 0; e < En; e++) logits[(size_t)t * En + e] = lg[e];
        int i0 = 0; float v0 = lg[0];
        #pragma unroll
        for (int e = 1; e < En; e++) if (lg[e] > v0) { v0 = lg[e]; i0 = e; }
        int i1 = -1; float v1 = -3.4e38f;
        #pragma unroll
        for (int e = 0; e < En; e++) if (e != i0 && lg[e] > v1) { v1 = lg[e]; i1 = e; }
        int p0 = t * 2, p1 = t * 2 + 1;
        g_scores[p0] = 1.f / (1.f + expf(-v0));
        g_scores[p1] = 1.f / (1.f + expf(-v1));
        int pos0 = atomicAdd(&g_cnt[i0], 1); g_list[i0 * Tn + pos0] = p0;
        int pos1 = atomicAdd(&g_cnt[i1], 1); g_list[i1 * Tn + pos1] = p1;
    }
}

// ---------------- generic tile GEMM body (R13-verified mainloop) ------------
// MODE 0: expert gate+up FUSED  A=x(gather)  B=gw|uw interleaved   K=2048 -> Hm
// MODE 1: shared gate+up FUSED  A=x          B=sgw|suw interleaved K=2048 -> Sm
// MODE 2: expert down           A=Hm         B=dw                  K=1024 -> g_Y
// MODE 3: shared down           A=Sm         B=sdw                 K=4096 -> out (+Y)
template<int MODE>
__device__ __forceinline__ void gemm_body(int e, int m0, int n0, int cnt,
                                          float* __restrict__ out, char* smem) {
    const uint32_t sb = smem_u32(smem);
    const int tid = threadIdx.x, wid = tid >> 5, lane = tid & 31;

    constexpr bool EXP = (MODE == 0 || MODE == 2);
    constexpr bool GUP = (MODE == 0 || MODE == 1);
    constexpr int  KT  = GUP ? 2048 : (MODE == 2 ? 1024 : 4096);
    constexpr int  NKC = KT / 32;

    int* sl = (int*)(smem + SM_LIST);
    if (EXP) {
        if (tid < 128) sl[tid] = (m0 + tid < cnt) ? g_list[e * Tn + m0 + tid] : -1;
        __syncthreads();
    }

    const int arow = tid >> 1, sub = tid & 1;
    bool aval = true;
    const __half *aF, *bF;
    if (MODE == 0) {
        int p = sl[arow]; aval = (p >= 0);
        aF = g_xF + (size_t)(aval ? (p >> 1) : 0) * Hd;
    } else if (MODE == 1) {
        aF = g_xF + (size_t)(m0 + arow) * Hd;
    } else if (MODE == 2) {
        int p = sl[arow]; aval = (p >= 0);
        aF = g_Hm + (size_t)(aval ? p : 0) * Id;
    } else {
        aF = g_Sm + (size_t)(m0 + arow) * ISd;
    }
    if (GUP) {
        const int j = (arow >> 3) & 1;
        const int srow = n0 + (arow >> 4) * 8 + (arow & 7);
        if (MODE == 0) bF = (j ? g_uwF : g_gwF) + ((size_t)e * Id + srow) * Hd;
        else           bF = (j ? g_suwF : g_sgwF) + (size_t)srow * Hd;
    } else if (MODE == 2) {
        bF = g_dwF + ((size_t)e * Hd + n0 + arow) * Id;
    } else {
        bF = g_sdwF + (size_t)(n0 + arow) * ISd;
    }

    const uint32_t avB = aval ? 16u : 0u;
    const uint32_t rsw = (uint32_t)((arow >> 1) & 3) << 4;
    const uint32_t s0 = ((uint32_t)(sub * 32))      ^ rsw;
    const uint32_t s1 = ((uint32_t)(sub * 32 + 16)) ^ rsw;
    const uint32_t aDst0 = sb + arow * 64;
    const uint32_t bDst0 = sb + SM_BOFF + arow * 64;

    const int wm = wid & 3, wn = wid >> 2;
    const uint32_t aLmRow = wm * 32 + (lane & 15);
    const uint32_t aLmB = aLmRow * 64;
    const uint32_t aswL = (uint32_t)((aLmRow >> 1) & 3) << 4;
    const uint32_t aLmK = (lane >> 4) * 16;
    const uint32_t bLmRow = wn * 64 + ((lane >> 4) & 1) * 8 + (lane & 7);
    const uint32_t bLmB = SM_BOFF + bLmRow * 64;
    const uint32_t bswL = (uint32_t)((bLmRow >> 1) & 3) << 4;
    const uint32_t bCol = ((lane >> 3) & 1) * 16;

    float acc[2][8][4];
    #pragma unroll
    for (int mt = 0; mt < 2; mt++)
        #pragma unroll
        for (int nt = 0; nt < 8; nt++)
            #pragma unroll
            for (int j = 0; j < 4; j++) acc[mt][nt][j] = 0.f;

    auto ISSUE = [&](int kc, int st) {
        const uint32_t aD = aDst0 + st * SM_STAGE;
        const uint32_t bD = bDst0 + st * SM_STAGE;
        const char* sA = (const char*)aF + kc * 64 + sub * 32;
        const char* sB = (const char*)bF + kc * 64 + sub * 32;
        cpa16(aD + s0, sA, avB);      cpa16(aD + s1, sA + 16, avB);
        cpa16(bD + s0, sB, 16u);      cpa16(bD + s1, sB + 16, 16u);
        cpcommit();
    };

    auto MMA = [&](int st) {
        const uint32_t aS = sb + st * SM_STAGE;
        #pragma unroll
        for (int h = 0; h < 2; h++) {
            uns Ah[2][4];
            #pragma unroll
            for (int mt = 0; mt < 2; mt++)
                ldsm4(Ah[mt], aS + aLmB + mt * 1024 + ((h * 32 + aLmK) ^ aswL));
            #pragma unroll
            for (int ntp = 0; ntp < 4; ntp++) {
                uns B4[4];
                ldsm4(B4, aS + bLmB + ntp * 1024 + ((h * 32 + bCol) ^ bswL));
                #pragma unroll
                for (int j = 0; j < 2; j++) {
                    const int nt = ntp * 2 + j;
                    #pragma unroll
                    for (int mt = 0; mt < 2; mt++)
                        mma16816(acc[mt][nt], Ah[mt], B4 + j * 2);
                }
            }
        }
    };

    ISSUE(0, 0); ISSUE(1, 1); ISSUE(2, 2);
    for (int kc = 0; kc < NKC; kc++) {
        if (kc + 1 >= NKC)      cpwait<0>();
        else if (kc + 2 >= NKC) cpwait<1>();
        else                    cpwait<2>();
        __syncthreads();
        if (kc + 3 < NKC) ISSUE(kc + 3, (kc + 3) & 3);
        MMA(kc & 3);
    }

    // ---- epilogue ----
    const int rb = wm * 32 + (lane >> 2);
    const int cq = (lane & 3) * 2;
    #pragma unroll
    for (int mt = 0; mt < 2; mt++) {
        #pragma unroll
        for (int rr = 0; rr < 2; rr++) {
            const int row = rb + mt * 16 + rr * 8;
            if (GUP) {
                float s; size_t base;
                if (MODE == 0) {
                    int p = sl[row];
                    if (p < 0) continue;
                    s = g_scores[p];
                    base = (size_t)p * Id;
                } else {
                    s = 1.f;
                    base = (size_t)(m0 + row) * ISd;
                }
                #pragma unroll
                for (int i = 0; i < 4; i++) {
                    float g0 = acc[mt][2 * i][rr * 2],     g1 = acc[mt][2 * i][rr * 2 + 1];
                    float u0 = acc[mt][2 * i + 1][rr * 2], u1 = acc[mt][2 * i + 1][rr * 2 + 1];
                    float h0, h1;
                    if (MODE == 0) { h0 = siluf(s * g0) * (s * u0); h1 = siluf(s * g1) * (s * u1); }
                    else           { h0 = siluf(g0) * u0;           h1 = siluf(g1) * u1; }
                    __half2 hp = __floats2half2_rn(h0, h1);
                    size_t idx = base + (size_t)(n0 + (wn * 4 + i) * 8 + cq);
                    if (MODE == 0) *(uns*)(g_Hm + idx) = *reinterpret_cast<uns*>(&hp);
                    else           *(uns*)(g_Sm + idx) = *reinterpret_cast<uns*>(&hp);
                }
            } else if (MODE == 2) {
                int p = sl[row];
                if (p < 0) continue;
                float* dst = g_Y + (size_t)p * Hd + n0 + wn * 64 + cq;
                #pragma unroll
                for (int nt = 0; nt < 8; nt++)
                    *(float2*)(dst + nt * 8) =
                        make_float2(acc[mt][nt][rr * 2], acc[mt][nt][rr * 2 + 1]);
            } else {
                const int t = m0 + row;
                size_t col = (size_t)(n0 + wn * 64 + cq);
                const float* y0 = g_Y + (size_t)(2 * t) * Hd + col;
                const float* y1 = g_Y + (size_t)(2 * t + 1) * Hd + col;
                float* dst = out + (size_t)t * Hd + col;
                #pragma unroll
                for (int nt = 0; nt < 8; nt++) {
                    float2 a = make_float2(acc[mt][nt][rr * 2], acc[mt][nt][rr * 2 + 1]);
                    float2 p0 = *(const float2*)(y0 + nt * 8);
                    float2 p1 = *(const float2*)(y1 + nt * 8);
                    a.x += p0.x + p1.x; a.y += p0.y + p1.y;
                    *(float2*)(dst + nt * 8) = a;
                }
            }
        }
    }
}

// ---------------- GEMM launch wrappers --------------------------------------
// Pass A: expert gate+up. grid (32, 16, 8)
__global__ __launch_bounds__(NTH, 2) void k_gemmA() {
    extern __shared__ __align__(1024) char smem[];
    const int e = blockIdx.z;
    const int cnt = g_cnt[e];
    const int m0 = blockIdx.x * BM;
    if (m0 >= cnt) return;
    gemm_body<0>(e, m0, blockIdx.y * 64, cnt, nullptr, smem);
}
// Pass B (merged): expert down (ids 0..4095) + shared gate+up (ids 4096..6143)
__global__ __launch_bounds__(NTH, 2) void k_gemmMid() {
    extern __shared__ __align__(1024) char smem[];
    const int id = blockIdx.x;
    if (id < 4096) {
        const int e = id >> 9;
        const int cnt = g_cnt[e];
        const int m0 = ((id >> 4) & 31) * BM;
        if (m0 >= cnt) return;
        gemm_body<2>(e, m0, (id & 15) * 128, cnt, nullptr, smem);
    } else {
        const int i2 = id - 4096;
        gemm_body<1>(0, (i2 >> 6) * BM, (i2 & 63) * 64, Tn, nullptr, smem);
    }
}
// Pass C: shared down + combine. grid (32, 16)
__global__ __launch_bounds__(NTH, 2) void k_gemmD(float* __restrict__ out) {
    extern __shared__ __align__(1024) char smem[];
    gemm_body<3>(0, blockIdx.x * BM, blockIdx.y * 128, Tn, out, smem);
}

// ---------------- launch ----------------------------------------------------
extern "C" void kernel_launch(void* const* d_in, const int* in_sizes, int n_in,
                              void* d_out, int out_size) {
    const float* x   = (const float*)d_in[0];
    const float* rw  = (const float*)d_in[1];
    const float* gw  = (const float*)d_in[2];
    const float* uw  = (const float*)d_in[3];
    const float* dw  = (const float*)d_in[4];
    const float* sgw = (const float*)d_in[5];
    const float* suw = (const float*)d_in[6];
    const float* sdw = (const float*)d_in[7];
    float* out = (float*)d_out;
    float* logits = out + (size_t)Tn * Hd;

    cudaFuncSetAttribute(k_gemmA,   cudaFuncAttributeMaxDynamicSharedMemorySize, SMEM_BYTES);
    cudaFuncSetAttribute(k_gemmMid, cudaFuncAttributeMaxDynamicSharedMemorySize, SMEM_BYTES);
    cudaFuncSetAttribute(k_gemmD,   cudaFuncAttributeMaxDynamicSharedMemorySize, SMEM_BYTES);

    k_zero<<<1, 32>>>();
    k_router<<<Tn, 256>>>(x, rw, logits);
    k_cvtall<<<20480, 256>>>((const float4*)x,  (const float4*)gw, (const float4*)uw,
                             (const float4*)dw, (const float4*)sgw,
                             (const float4*)suw, (const float4*)sdw);

    k_gemmA<<<dim3(Tn / BM, Id / 64, En), NTH, SMEM_BYTES>>>();
    k_gemmMid<<<6144, NTH, SMEM_BYTES>>>();
    k_gemmD<<<dim3(Tn / BM, Hd / 128), NTH, SMEM_BYTES>>>(out);
}

// round 17
// speedup vs baseline: 1.1492x; 1.0987x over previous
#include <cuda_runtime.h>
#include <cuda_fp16.h>
#include <cstdint>

#define Tn  4096
#define Hd  2048
#define En  8
#define Id  1024
#define ISd 4096

#define BM 128
#define NTH 256

// smem: 5 stages of 16KB (A 8KB fp16 + B 8KB fp16); list after.
#define SM_STAGE 16384
#define SM_BOFF  8192
#define SM_LIST  81920
#define SMEM_BYTES 82432

typedef unsigned uns;

// ---------------- device scratch -------------------------------------------
__device__ int   g_cnt[En];
__device__ int   g_list[En * Tn];
__device__ float g_scores[Tn * 2];
__device__ __half g_Hm[(size_t)Tn * 2 * Id];
__device__ __half g_Sm[(size_t)Tn * ISd];
__device__ float g_Y[(size_t)Tn * 2 * Hd];
// pre-converted fp16 operands
__device__ __half g_xF[(size_t)Tn * Hd];
__device__ __half g_gwF[(size_t)En * Id * Hd];
__device__ __half g_uwF[(size_t)En * Id * Hd];
__device__ __half g_dwF[(size_t)En * Hd * Id];
__device__ __half g_sgwF[(size_t)ISd * Hd];
__device__ __half g_suwF[(size_t)ISd * Hd];
__device__ __half g_sdwF[(size_t)Hd * ISd];

// ---------------- helpers --------------------------------------------------
__device__ __forceinline__ uint32_t smem_u32(const void* p) {
    uint32_t a;
    asm("{ .reg .u64 t; cvta.to.shared.u64 t, %1; cvt.u32.u64 %0, t; }" : "=r"(a) : "l"(p));
    return a;
}
__device__ __forceinline__ void ldsm4(uns r[4], uint32_t a) {
    asm volatile("ldmatrix.sync.aligned.m8n8.x4.shared.b16 {%0,%1,%2,%3}, [%4];"
        : "=r"(r[0]), "=r"(r[1]), "=r"(r[2]), "=r"(r[3]) : "r"(a));
}
__device__ __forceinline__ void mma16816(float c[4], const uns a[4], const uns b[2]) {
    asm volatile("mma.sync.aligned.m16n8k16.row.col.f32.f16.f16.f32 "
        "{%0,%1,%2,%3}, {%4,%5,%6,%7}, {%8,%9}, {%0,%1,%2,%3};"
        : "+f"(c[0]), "+f"(c[1]), "+f"(c[2]), "+f"(c[3])
        : "r"(a[0]), "r"(a[1]), "r"(a[2]), "r"(a[3]), "r"(b[0]), "r"(b[1]));
}
// L1-bypass (L2-cached) 16B async copy: weights/activations have no L1 reuse.
__device__ __forceinline__ void cpa16(uint32_t d, const void* s, uint32_t bytes) {
    asm volatile("cp.async.cg.shared.global [%0], [%1], 16, %2;"
        :: "r"(d), "l"(s), "r"(bytes) : "memory");
}
__device__ __forceinline__ void cpcommit() {
    asm volatile("cp.async.commit_group;" ::: "memory");
}
template<int N> __device__ __forceinline__ void cpwait() {
    asm volatile("cp.async.wait_group %0;" :: "n"(N) : "memory");
}
__device__ __forceinline__ float siluf(float x) { return x / (1.f + expf(-x)); }

// ---------------- fused cvt (fp32->fp16, 7 tensors) + router -----------------
// blocks [0, 20480): convert; blocks [20480, 24576): router (one block/token).
__global__ void k_cvtrt(const float4* __restrict__ x,  const float4* __restrict__ gw,
                        const float4* __restrict__ uw, const float4* __restrict__ dw,
                        const float4* __restrict__ sgw, const float4* __restrict__ suw,
                        const float4* __restrict__ sdw,
                        const float* __restrict__ rw,  float* __restrict__ logits) {
    __shared__ float lg[En];
    const unsigned M = 1u << 20;
    if (blockIdx.x < 20480u) {
        unsigned b = blockIdx.x * 1024u;
        const float4* src; __half* dsth; unsigned w0;
        if      (b < 2*M)  { src = x;   dsth = g_xF;   w0 = b; }
        else if (b < 6*M)  { src = gw;  dsth = g_gwF;  w0 = b - 2*M; }
        else if (b < 10*M) { src = uw;  dsth = g_uwF;  w0 = b - 6*M; }
        else if (b < 14*M) { src = dw;  dsth = g_dwF;  w0 = b - 10*M; }
        else if (b < 16*M) { src = sgw; dsth = g_sgwF; w0 = b - 14*M; }
        else if (b < 18*M) { src = suw; dsth = g_suwF; w0 = b - 16*M; }
        else               { src = sdw; dsth = g_sdwF; w0 = b - 18*M; }
        uint2* dst = (uint2*)dsth;
        unsigned w = w0 + threadIdx.x;
        float4 v0 = src[w];
        float4 v1 = src[w + 256];
        float4 v2 = src[w + 512];
        float4 v3 = src[w + 768];
        __half2 a0 = __floats2half2_rn(v0.x, v0.y), b0h = __floats2half2_rn(v0.z, v0.w);
        dst[w]       = make_uint2(*(uns*)&a0, *(uns*)&b0h);
        __half2 a1 = __floats2half2_rn(v1.x, v1.y), b1h = __floats2half2_rn(v1.z, v1.w);
        dst[w + 256] = make_uint2(*(uns*)&a1, *(uns*)&b1h);
        __half2 a2 = __floats2half2_rn(v2.x, v2.y), b2h = __floats2half2_rn(v2.z, v2.w);
        dst[w + 512] = make_uint2(*(uns*)&a2, *(uns*)&b2h);
        __half2 a3 = __floats2half2_rn(v3.x, v3.y), b3h = __floats2half2_rn(v3.z, v3.w);
        dst[w + 768] = make_uint2(*(uns*)&a3, *(uns*)&b3h);
        return;
    }
    // ---- router body ----
    int t = (int)(blockIdx.x - 20480u);
    int w = threadIdx.x >> 5, lane = threadIdx.x & 31;
    const float* xt = (const float*)x + (size_t)t * Hd;
    const float* we = rw + (size_t)w * Hd;
    float s = 0.f;
    for (int i = lane * 4; i < Hd; i += 128) {
        float4 xv = *(const float4*)(xt + i);
        float4 wv = *(const float4*)(we + i);
        s += xv.x * wv.x + xv.y * wv.y + xv.z * wv.z + xv.w * wv.w;
    }
    #pragma unroll
    for (int o = 16; o; o >>= 1) s += __shfl_xor_sync(0xffffffffu, s, o);
    if (!lane) lg[w] = s;
    __syncthreads();
    if (threadIdx.x == 0) {
        #pragma unroll
        for (int e = 0; e < En; e++) logits[(size_t)t * En + e] = lg[e];
        int i0 = 0; float v0 = lg[0];
        #pragma unroll
        for (int e = 1; e < En; e++) if (lg[e] > v0) { v0 = lg[e]; i0 = e; }
        int i1 = -1; float v1 = -3.4e38f;
        #pragma unroll
        for (int e = 0; e < En; e++) if (e != i0 && lg[e] > v1) { v1 = lg[e]; i1 = e; }
        int p0 = t * 2, p1 = t * 2 + 1;
        g_scores[p0] = 1.f / (1.f + expf(-v0));
        g_scores[p1] = 1.f / (1.f + expf(-v1));
        int pos0 = atomicAdd(&g_cnt[i0], 1); g_list[i0 * Tn + pos0] = p0;
        int pos1 = atomicAdd(&g_cnt[i1], 1); g_list[i1 * Tn + pos1] = p1;
    }
}

__global__ void k_zero() {
    if (threadIdx.x < En) g_cnt[threadIdx.x] = 0;
}

// ---------------- generic tile GEMM body ------------------------------------
// MODE 0: expert gate+up FUSED  A=x(gather)  B=gw|uw interleaved   K=2048 -> Hm
// MODE 1: shared gate+up FUSED  A=x          B=sgw|suw interleaved K=2048 -> Sm
// MODE 2: expert down           A=Hm         B=dw                  K=1024 -> g_Y
// MODE 3: shared down           A=Sm         B=sdw                 K=4096 -> out (+Y)
template<int MODE>
__device__ __forceinline__ void gemm_body(int e, int m0, int n0, int cnt,
                                          float* __restrict__ out, char* smem) {
    const uint32_t sb = smem_u32(smem);
    const int tid = threadIdx.x, wid = tid >> 5, lane = tid & 31;

    constexpr bool EXP = (MODE == 0 || MODE == 2);
    constexpr bool GUP = (MODE == 0 || MODE == 1);
    constexpr int  KT  = GUP ? 2048 : (MODE == 2 ? 1024 : 4096);
    constexpr int  NKC = KT / 32;

    int* sl = (int*)(smem + SM_LIST);
    if (EXP) {
        if (tid < 128) sl[tid] = (m0 + tid < cnt) ? g_list[e * Tn + m0 + tid] : -1;
        __syncthreads();
    }

    const int arow = tid >> 1, sub = tid & 1;
    bool aval = true;
    const __half *aF, *bF;
    if (MODE == 0) {
        int p = sl[arow]; aval = (p >= 0);
        aF = g_xF + (size_t)(aval ? (p >> 1) : 0) * Hd;
    } else if (MODE == 1) {
        aF = g_xF + (size_t)(m0 + arow) * Hd;
    } else if (MODE == 2) {
        int p = sl[arow]; aval = (p >= 0);
        aF = g_Hm + (size_t)(aval ? p : 0) * Id;
    } else {
        aF = g_Sm + (size_t)(m0 + arow) * ISd;
    }
    if (GUP) {
        const int j = (arow >> 3) & 1;
        const int srow = n0 + (arow >> 4) * 8 + (arow & 7);
        if (MODE == 0) bF = (j ? g_uwF : g_gwF) + ((size_t)e * Id + srow) * Hd;
        else           bF = (j ? g_suwF : g_sgwF) + (size_t)srow * Hd;
    } else if (MODE == 2) {
        bF = g_dwF + ((size_t)e * Hd + n0 + arow) * Id;
    } else {
        bF = g_sdwF + (size_t)(n0 + arow) * ISd;
    }

    const uint32_t avB = aval ? 16u : 0u;
    const uint32_t rsw = (uint32_t)((arow >> 1) & 3) << 4;
    const uint32_t s0 = ((uint32_t)(sub * 32))      ^ rsw;
    const uint32_t s1 = ((uint32_t)(sub * 32 + 16)) ^ rsw;
    const uint32_t aDst0 = sb + arow * 64;
    const uint32_t bDst0 = sb + SM_BOFF + arow * 64;

    const int wm = wid & 3, wn = wid >> 2;
    const uint32_t aLmRow = wm * 32 + (lane & 15);
    const uint32_t aLmB = aLmRow * 64;
    const uint32_t aswL = (uint32_t)((aLmRow >> 1) & 3) << 4;
    const uint32_t aLmK = (lane >> 4) * 16;
    const uint32_t bLmRow = wn * 64 + ((lane >> 4) & 1) * 8 + (lane & 7);
    const uint32_t bLmB = SM_BOFF + bLmRow * 64;
    const uint32_t bswL = (uint32_t)((bLmRow >> 1) & 3) << 4;
    const uint32_t bCol = ((lane >> 3) & 1) * 16;

    float acc[2][8][4];
    #pragma unroll
    for (int mt = 0; mt < 2; mt++)
        #pragma unroll
        for (int nt = 0; nt < 8; nt++)
            #pragma unroll
            for (int j = 0; j < 4; j++) acc[mt][nt][j] = 0.f;

    auto ISSUE = [&](int kc, int st) {
        const uint32_t aD = aDst0 + st * SM_STAGE;
        const uint32_t bD = bDst0 + st * SM_STAGE;
        const char* sA = (const char*)aF + kc * 64 + sub * 32;
        const char* sB = (const char*)bF + kc * 64 + sub * 32;
        cpa16(aD + s0, sA, avB);      cpa16(aD + s1, sA + 16, avB);
        cpa16(bD + s0, sB, 16u);      cpa16(bD + s1, sB + 16, 16u);
        cpcommit();
    };

    auto MMA = [&](int st) {
        const uint32_t aS = sb + st * SM_STAGE;
        #pragma unroll
        for (int h = 0; h < 2; h++) {
            uns Ah[2][4];
            #pragma unroll
            for (int mt = 0; mt < 2; mt++)
                ldsm4(Ah[mt], aS + aLmB + mt * 1024 + ((h * 32 + aLmK) ^ aswL));
            #pragma unroll
            for (int ntp = 0; ntp < 4; ntp++) {
                uns B4[4];
                ldsm4(B4, aS + bLmB + ntp * 1024 + ((h * 32 + bCol) ^ bswL));
                #pragma unroll
                for (int j = 0; j < 2; j++) {
                    const int nt = ntp * 2 + j;
                    #pragma unroll
                    for (int mt = 0; mt < 2; mt++)
                        mma16816(acc[mt][nt], Ah[mt], B4 + j * 2);
                }
            }
        }
    };

    // 5-stage pipeline, one barrier per chunk, up to 4 chunks in flight.
    ISSUE(0, 0); ISSUE(1, 1); ISSUE(2, 2); ISSUE(3, 3);
    int stIss = 4, stCon = 0;
    for (int kc = 0; kc < NKC; kc++) {
        if (kc + 1 >= NKC)      cpwait<0>();
        else if (kc + 2 >= NKC) cpwait<1>();
        else if (kc + 3 >= NKC) cpwait<2>();
        else                    cpwait<3>();
        __syncthreads();
        if (kc + 4 < NKC) {
            ISSUE(kc + 4, stIss);
            if (++stIss == 5) stIss = 0;
        }
        MMA(stCon);
        if (++stCon == 5) stCon = 0;
    }

    // ---- epilogue ----
    const int rb = wm * 32 + (lane >> 2);
    const int cq = (lane & 3) * 2;
    #pragma unroll
    for (int mt = 0; mt < 2; mt++) {
        #pragma unroll
        for (int rr = 0; rr < 2; rr++) {
            const int row = rb + mt * 16 + rr * 8;
            if (GUP) {
                float s; size_t base;
                if (MODE == 0) {
                    int p = sl[row];
                    if (p < 0) continue;
                    s = g_scores[p];
                    base = (size_t)p * Id;
                } else {
                    s = 1.f;
                    base = (size_t)(m0 + row) * ISd;
                }
                #pragma unroll
                for (int i = 0; i < 4; i++) {
                    float g0 = acc[mt][2 * i][rr * 2],     g1 = acc[mt][2 * i][rr * 2 + 1];
                    float u0 = acc[mt][2 * i + 1][rr * 2], u1 = acc[mt][2 * i + 1][rr * 2 + 1];
                    float h0, h1;
                    if (MODE == 0) { h0 = siluf(s * g0) * (s * u0); h1 = siluf(s * g1) * (s * u1); }
                    else           { h0 = siluf(g0) * u0;           h1 = siluf(g1) * u1; }
                    __half2 hp = __floats2half2_rn(h0, h1);
                    size_t idx = base + (size_t)(n0 + (wn * 4 + i) * 8 + cq);
                    if (MODE == 0) *(uns*)(g_Hm + idx) = *reinterpret_cast<uns*>(&hp);
                    else           *(uns*)(g_Sm + idx) = *reinterpret_cast<uns*>(&hp);
                }
            } else if (MODE == 2) {
                int p = sl[row];
                if (p < 0) continue;
                float* dst = g_Y + (size_t)p * Hd + n0 + wn * 64 + cq;
                #pragma unroll
                for (int nt = 0; nt < 8; nt++)
                    *(float2*)(dst + nt * 8) =
                        make_float2(acc[mt][nt][rr * 2], acc[mt][nt][rr * 2 + 1]);
            } else {
                const int t = m0 + row;
                size_t col = (size_t)(n0 + wn * 64 + cq);
                const float* y0 = g_Y + (size_t)(2 * t) * Hd + col;
                const float* y1 = g_Y + (size_t)(2 * t + 1) * Hd + col;
                float* dst = out + (size_t)t * Hd + col;
                #pragma unroll
                for (int nt = 0; nt < 8; nt++) {
                    float2 a = make_float2(acc[mt][nt][rr * 2], acc[mt][nt][rr * 2 + 1]);
                    float2 p0 = *(const float2*)(y0 + nt * 8);
                    float2 p1 = *(const float2*)(y1 + nt * 8);
                    a.x += p0.x + p1.x; a.y += p0.y + p1.y;
                    *(float2*)(dst + nt * 8) = a;
                }
            }
        }
    }
}

// ---------------- GEMM launch wrappers --------------------------------------
__global__ __launch_bounds__(NTH, 2) void k_gemmA() {
    extern __shared__ __align__(1024) char smem[];
    const int e = blockIdx.z;
    const int cnt = g_cnt[e];
    const int m0 = blockIdx.x * BM;
    if (m0 >= cnt) return;
    gemm_body<0>(e, m0, blockIdx.y * 64, cnt, nullptr, smem);
}
__global__ __launch_bounds__(NTH, 2) void k_gemmMid() {
    extern __shared__ __align__(1024) char smem[];
    const int id = blockIdx.x;
    if (id < 4096) {
        const int e = id >> 9;
        const int cnt = g_cnt[e];
        const int m0 = ((id >> 4) & 31) * BM;
        if (m0 >= cnt) return;
        gemm_body<2>(e, m0, (id & 15) * 128, cnt, nullptr, smem);
    } else {
        const int i2 = id - 4096;
        gemm_body<1>(0, (i2 >> 6) * BM, (i2 & 63) * 64, Tn, nullptr, smem);
    }
}
__global__ __launch_bounds__(NTH, 2) void k_gemmD(float* __restrict__ out) {
    extern __shared__ __align__(1024) char smem[];
    gemm_body<3>(0, blockIdx.x * BM, blockIdx.y * 128, Tn, out, smem);
}

// ---------------- launch ----------------------------------------------------
extern "C" void kernel_launch(void* const* d_in, const int* in_sizes, int n_in,
                              void* d_out, int out_size) {
    const float* x   = (const float*)d_in[0];
    const float* rw  = (const float*)d_in[1];
    const float* gw  = (const float*)d_in[2];
    const float* uw  = (const float*)d_in[3];
    const float* dw  = (const float*)d_in[4];
    const float* sgw = (const float*)d_in[5];
    const float* suw = (const float*)d_in[6];
    const float* sdw = (const float*)d_in[7];
    float* out = (float*)d_out;
    float* logits = out + (size_t)Tn * Hd;

    cudaFuncSetAttribute(k_gemmA,   cudaFuncAttributeMaxDynamicSharedMemorySize, SMEM_BYTES);
    cudaFuncSetAttribute(k_gemmMid, cudaFuncAttributeMaxDynamicSharedMemorySize, SMEM_BYTES);
    cudaFuncSetAttribute(k_gemmD,   cudaFuncAttributeMaxDynamicSharedMemorySize, SMEM_BYTES);

    k_zero<<<1, 32>>>();
    k_cvtrt<<<24576, 256>>>((const float4*)x,  (const float4*)gw, (const float4*)uw,
                            (const float4*)dw, (const float4*)sgw,
                            (const float4*)suw, (const float4*)sdw, rw, logits);

    k_gemmA<<<dim3(Tn / BM, Id / 64, En), NTH, SMEM_BYTES>>>();
    k_gemmMid<<<6144, NTH, SMEM_BYTES>>>();
    k_gemmD<<<dim3(Tn / BM, Hd / 128), NTH, SMEM_BYTES>>>(out);
}